// round 8
// baseline (speedup 1.0000x reference)
#include <cuda_runtime.h>

// Jacobi 5-iteration temporally-blocked cross stencil, sm_103a.
// Cross-sweep register forwarding: every sweep uses the same 400-thread
// 4x4-block mapping, so each thread's outputs become the center rows of its
// next-sweep window (registers), and only 4 vertical halo rows + horizontal
// float2s come from smem. Final sweep stores straight to global (no STS).
// rhs streamed from L2 each sweep. 3 CTAs/SM.
// B=16, H=W=1024, radius-2 cross, boundary ring (width 2) frozen.

constexpr int HH  = 1024;
constexpr int WW  = 1024;
constexpr int NB  = 16;
constexpr int T   = 64;             // output tile
constexpr int RAD = 10;             // 2*5 halo
constexpr int L   = 84;             // local extent
constexpr int LP  = 84;             // stride
constexpr int NT  = 448;            // 14 warps; 400 active in sweeps
constexpr int SMEM_BYTES = (2 * L * LP + 4) * 4;   // 56,480 B -> 3 CTAs/SM

struct Coef { float dinv, k1x, k2x, k1y, k2y; };

template<bool EDGE>
__device__ __forceinline__ float4 rr_load(const float* __restrict__ rg,
                                          int gi, int gj)
{
    if (EDGE) {
        const bool ok = ((unsigned)gi < (unsigned)HH) && ((unsigned)gj < (unsigned)WW);
        return ok ? *(const float4*)(rg + (size_t)gi * WW + gj)
                  : make_float4(0.f, 0.f, 0.f, 0.f);
    }
    return *(const float4*)(rg + (size_t)gi * WW + gj);
}

// One output row from 5 vertical window rows (w2 = center), horizontal halos,
// rhs; EDGE freezes boundary-ring cells to the old center value.
template<bool EDGE>
__device__ __forceinline__ float4 row_update(const float4 w0, const float4 w1,
                                             const float4 w2, const float4 w3,
                                             const float4 w4,
                                             const float2 hl, const float2 hr,
                                             const float4 rr, const Coef c,
                                             int gi, int gj)
{
    const float h0 = hl.x, h1 = hl.y, h2 = w2.x, h3 = w2.y;
    const float h4 = w2.z, h5 = w2.w, h6 = hr.x, h7 = hr.y;
    float4 o;
    o.x = fmaf(rr.x, c.dinv, -(c.k2x * (w0.x + w4.x) + c.k1x * (w1.x + w3.x)
                             + c.k2y * (h0 + h4) + c.k1y * (h1 + h3)));
    o.y = fmaf(rr.y, c.dinv, -(c.k2x * (w0.y + w4.y) + c.k1x * (w1.y + w3.y)
                             + c.k2y * (h1 + h5) + c.k1y * (h2 + h4)));
    o.z = fmaf(rr.z, c.dinv, -(c.k2x * (w0.z + w4.z) + c.k1x * (w1.z + w3.z)
                             + c.k2y * (h2 + h6) + c.k1y * (h3 + h5)));
    o.w = fmaf(rr.w, c.dinv, -(c.k2x * (w0.w + w4.w) + c.k1x * (w1.w + w3.w)
                             + c.k2y * (h3 + h7) + c.k1y * (h4 + h6)));
    if (EDGE) {
        const bool ir = (unsigned)(gi - 2) < (unsigned)(HH - 4);
        o.x = (ir && (unsigned)(gj + 0 - 2) < (unsigned)(WW - 4)) ? o.x : w2.x;
        o.y = (ir && (unsigned)(gj + 1 - 2) < (unsigned)(WW - 4)) ? o.y : w2.y;
        o.z = (ir && (unsigned)(gj + 2 - 2) < (unsigned)(WW - 4)) ? o.z : w2.z;
        o.w = (ir && (unsigned)(gj + 3 - 2) < (unsigned)(WW - 4)) ? o.w : w2.w;
    }
    return o;
}

// One sweep over the thread's 4x4 block. o[] holds this thread's 4 center
// rows on entry (FIRST loads them from cur instead) and its 4 new rows on
// exit. LAST stores to global instead of smem.
template<bool EDGE, bool FIRST, bool LAST>
__device__ __forceinline__ void sweep_f(const float* __restrict__ cur,
                                        float* __restrict__ nxt,
                                        const float* __restrict__ rg,
                                        float* __restrict__ ob,
                                        float4 (&o)[4],
                                        int li0, int lj, int gi0, int gj,
                                        const Coef c)
{
    const float* base = cur + li0 * LP + lj;
    if (FIRST) {
        o[0] = *(const float4*)(base);
        o[1] = *(const float4*)(base + LP);
        o[2] = *(const float4*)(base + 2 * LP);
        o[3] = *(const float4*)(base + 3 * LP);
    }
    const float4 rm2 = *(const float4*)(base - 2 * LP);
    const float4 rm1 = *(const float4*)(base - LP);
    const float4 rp4 = *(const float4*)(base + 4 * LP);
    const float4 rp5 = *(const float4*)(base + 5 * LP);

    const float2 hl0 = *(const float2*)(base - 2);
    const float2 hr0 = *(const float2*)(base + 4);
    const float2 hl1 = *(const float2*)(base + LP - 2);
    const float2 hr1 = *(const float2*)(base + LP + 4);
    const float2 hl2 = *(const float2*)(base + 2 * LP - 2);
    const float2 hr2 = *(const float2*)(base + 2 * LP + 4);
    const float2 hl3 = *(const float2*)(base + 3 * LP - 2);
    const float2 hr3 = *(const float2*)(base + 3 * LP + 4);

    const float4 rr0 = rr_load<EDGE>(rg, gi0 + 0, gj);
    const float4 rr1 = rr_load<EDGE>(rg, gi0 + 1, gj);
    const float4 rr2 = rr_load<EDGE>(rg, gi0 + 2, gj);
    const float4 rr3 = rr_load<EDGE>(rg, gi0 + 3, gj);

    const float4 n0 = row_update<EDGE>(rm2,  rm1,  o[0], o[1], o[2], hl0, hr0, rr0, c, gi0 + 0, gj);
    const float4 n1 = row_update<EDGE>(rm1,  o[0], o[1], o[2], o[3], hl1, hr1, rr1, c, gi0 + 1, gj);
    const float4 n2 = row_update<EDGE>(o[0], o[1], o[2], o[3], rp4,  hl2, hr2, rr2, c, gi0 + 2, gj);
    const float4 n3 = row_update<EDGE>(o[1], o[2], o[3], rp4,  rp5,  hl3, hr3, rr3, c, gi0 + 3, gj);

    if (LAST) {
        // output region [10,74)^2 falls exactly on whole 4x4 blocks
        if (li0 >= 10 && li0 <= 70 && lj >= 10 && lj <= 70) {
            *(float4*)(ob + (size_t)(gi0 + 0) * WW + gj) = n0;
            *(float4*)(ob + (size_t)(gi0 + 1) * WW + gj) = n1;
            *(float4*)(ob + (size_t)(gi0 + 2) * WW + gj) = n2;
            *(float4*)(ob + (size_t)(gi0 + 3) * WW + gj) = n3;
        }
    } else {
        float* nb = nxt + li0 * LP + lj;
        *(float4*)(nb)          = n0;
        *(float4*)(nb + LP)     = n1;
        *(float4*)(nb + 2 * LP) = n2;
        *(float4*)(nb + 3 * LP) = n3;
        o[0] = n0; o[1] = n1; o[2] = n2; o[3] = n3;
    }
}

template<bool EDGE>
__device__ __forceinline__ void run_all(float* A, float* Bf, const float* rg,
                                        float* ob, int tid, int ti, int tj,
                                        const Coef c)
{
    const bool active = tid < 400;
    const int rbk = tid / 20;
    const int cg  = tid - rbk * 20;
    const int li0 = 2 + 4 * rbk;
    const int lj  = 2 + 4 * cg;
    const int gi0 = ti + li0 - RAD;
    const int gj  = tj + lj - RAD;

    float4 o[4];
    if (active) sweep_f<EDGE, true,  false>(A,  Bf, rg, ob, o, li0, lj, gi0, gj, c);
    __syncthreads();
    if (active) sweep_f<EDGE, false, false>(Bf, A,  rg, ob, o, li0, lj, gi0, gj, c);
    __syncthreads();
    if (active) sweep_f<EDGE, false, false>(A,  Bf, rg, ob, o, li0, lj, gi0, gj, c);
    __syncthreads();
    if (active) sweep_f<EDGE, false, false>(Bf, A,  rg, ob, o, li0, lj, gi0, gj, c);
    __syncthreads();
    if (active) sweep_f<EDGE, false, true >(A,  Bf, rg, ob, o, li0, lj, gi0, gj, c);
}

__global__ void __launch_bounds__(NT, 3)
jacobi5_fused(const float* __restrict__ g0,
              const float* __restrict__ rhs,
              const float* __restrict__ dx,
              float* __restrict__ out)
{
    extern __shared__ float sm[];
    float* A  = sm + 2;             // +2-word shift: cols lj=2+4m are 16B aligned
    float* Bf = sm + 2 + L * LP;

    const int b  = blockIdx.z;
    const int ti = blockIdx.y * T;
    const int tj = blockIdx.x * T;

    const float ix = 1.0f / dx[2 * b + 0];
    const float iy = 1.0f / dx[2 * b + 1];
    const float sx = ix * ix;
    const float sy = iy * iy;
    Coef c;
    c.dinv = 1.0f / (-2.5f * (sx + sy));
    c.k1x = c.dinv * sx * (4.0f / 3.0f);
    c.k2x = c.dinv * sx * (-1.0f / 12.0f);
    c.k1y = c.dinv * sy * (4.0f / 3.0f);
    c.k2y = c.dinv * sy * (-1.0f / 12.0f);

    const float* gb = g0  + (size_t)b * HH * WW;
    const float* rg = rhs + (size_t)b * HH * WW;
    float*       ob = out + (size_t)b * HH * WW;

    const int tid = threadIdx.x;
    const bool edge = (blockIdx.x == 0) | (blockIdx.x == gridDim.x - 1) |
                      (blockIdx.y == 0) | (blockIdx.y == gridDim.y - 1);

    // ---- load g halo into A ----
    if (edge) {
        for (int idx = tid; idx < L * L; idx += NT) {
            const int li = idx / L, lj = idx - (idx / L) * L;
            const int gi = ti + li - RAD, gj = tj + lj - RAD;
            float v = 0.0f;
            if (((unsigned)gi < (unsigned)HH) && ((unsigned)gj < (unsigned)WW))
                v = gb[(size_t)gi * WW + gj];
            A[li * LP + lj] = v;
        }
    } else {
        // float2-vectorized: 84 rows x 42 groups; gj even -> 8B aligned both sides
        constexpr int NGB = L / 2;                    // 42
        for (int idx = tid; idx < L * NGB; idx += NT) {
            const int li = idx / NGB, m = idx - (idx / NGB) * NGB;
            const int lj = 2 * m;
            const int gi = ti + li - RAD, gj = tj + lj - RAD;
            const float2 v = *(const float2*)(gb + (size_t)gi * WW + gj);
            *(float2*)(A + li * LP + lj) = v;
        }
    }
    __syncthreads();

    if (edge)
        run_all<true >(A, Bf, rg, ob, tid, ti, tj, c);
    else
        run_all<false>(A, Bf, rg, ob, tid, ti, tj, c);
}

extern "C" void kernel_launch(void* const* d_in, const int* in_sizes, int n_in,
                              void* d_out, int out_size) {
    const float* g0  = (const float*)d_in[0];
    const float* rhs = (const float*)d_in[1];
    const float* dx  = (const float*)d_in[2];
    float* out = (float*)d_out;

    cudaFuncSetAttribute(jacobi5_fused,
                         cudaFuncAttributeMaxDynamicSharedMemorySize, SMEM_BYTES);

    dim3 grid(WW / T, HH / T, NB);   // 16 x 16 x 16
    jacobi5_fused<<<grid, NT, SMEM_BYTES>>>(g0, rhs, dx, out);
}